// round 3
// baseline (speedup 1.0000x reference)
#include <cuda_runtime.h>

typedef unsigned long long ull;

#define NTHR   256
#define TLEN   168
#define SEQ    169
#define NB     32
#define GRID   128
#define NSTEPS 24
#define WSTR   193
#define GSTR   36

// relu(h1) staging: [GRID][TLEN][64][NB]
__device__ float g_r1[(size_t)GRID * TLEN * 64 * NB];

static __device__ __forceinline__ void ffma2(ull& d, ull a, ull b) {
    asm("fma.rn.f32x2 %0, %1, %2, %0;" : "+l"(d) : "l"(a), "l"(b));
}
static __device__ __forceinline__ ull splat(float w) {
    ull r; asm("mov.b64 %0, {%1, %1};" : "=l"(r) : "f"(w)); return r;
}
static __device__ __forceinline__ float rcp_fast(float x) {
    float r; asm("rcp.approx.f32 %0, %1;" : "=f"(r) : "f"(x)); return r;
}
static __device__ __forceinline__ float sig_fast(float x) { return rcp_fast(1.0f + __expf(-x)); }
static __device__ __forceinline__ float tanh_fast(float x) { return fmaf(2.0f, sig_fast(2.0f * x), -1.0f); }

// ---------------- layer-1 phase: matvec(half xoff) overlapped with act(half yoff, time ty) ----------------
static __device__ __forceinline__ void phaseL1(
    bool do_mv, bool do_act,
    const float* __restrict__ Wt, float* __restrict__ hh, float* __restrict__ gsh,
    const float* __restrict__ win, const float* __restrict__ b1s, const float* __restrict__ wi1s,
    int r4, int c4, int au, int ab,
    int xoff, int yoff, int ty, int step, float* cst, size_t g_base)
{
    float G[16];
    float xt = 0.0f;
    if (do_act) {
        xt = win[(yoff + ab) * WSTR + step + ty];
        #pragma unroll
        for (int q = 0; q < 4; q++) {
            int u = au + 16 * q;
            G[4*q+0] = gsh[(u      ) * GSTR + yoff + ab];
            G[4*q+1] = gsh[(u +  64) * GSTR + yoff + ab];
            G[4*q+2] = gsh[(u + 128) * GSTR + yoff + ab];
            G[4*q+3] = gsh[(u + 192) * GSTR + yoff + ab];
        }
    }
    ull a0=0,a1=0,a2=0,a3=0,a4=0,a5=0,a6=0,a7=0;
    const float4*     wp = (const float4*)Wt + r4;
    const ulonglong2* hp = (const ulonglong2*)hh + ((xoff >> 2) + c4);

    #pragma unroll
    for (int q = 0; q < 4; q++) {
        if (do_mv) {
            #pragma unroll
            for (int k = 16 * q; k < 16 * q + 16; k++) {
                float4 w = wp[k * 64];
                ulonglong2 hv = hp[k * 8];
                ull w0 = splat(w.x), w1 = splat(w.y), w2 = splat(w.z), w3 = splat(w.w);
                ffma2(a0, w0, hv.x); ffma2(a1, w0, hv.y);
                ffma2(a2, w1, hv.x); ffma2(a3, w1, hv.y);
                ffma2(a4, w2, hv.x); ffma2(a5, w2, hv.y);
                ffma2(a6, w3, hv.x); ffma2(a7, w3, hv.y);
            }
        }
        if (do_act) {
            int u = au + 16 * q;
            float gi = G[4*q+0] + fmaf(xt, wi1s[u      ], b1s[u      ]);
            float gf = G[4*q+1] + fmaf(xt, wi1s[u +  64], b1s[u +  64]);
            float gg = G[4*q+2] + fmaf(xt, wi1s[u + 128], b1s[u + 128]);
            float go = G[4*q+3] + fmaf(xt, wi1s[u + 192], b1s[u + 192]);
            float cn = fmaf(sig_fast(gf), cst[q], sig_fast(gi) * tanh_fast(gg));
            cst[q] = cn;
            float h = sig_fast(go) * tanh_fast(cn);
            hh[u * NB + yoff + ab] = h;
            g_r1[g_base + (size_t)ty * 2048 + u * NB + yoff + ab] = fmaxf(h, 0.0f);
        }
    }
    if (do_mv) {
        float* g0 = gsh + (r4 * 4) * GSTR + xoff + c4 * 4;
        *(ulonglong2*)(g0           ) = make_ulonglong2(a0, a1);
        *(ulonglong2*)(g0 +   GSTR  ) = make_ulonglong2(a2, a3);
        *(ulonglong2*)(g0 + 2*GSTR  ) = make_ulonglong2(a4, a5);
        *(ulonglong2*)(g0 + 3*GSTR  ) = make_ulonglong2(a6, a7);
    }
}

// ---------------- layer-2 phase: K=128 matvec overlapped with act + r1 feed/prefetch ----------------
static __device__ __forceinline__ void phaseL2(
    bool do_mv, bool do_act,
    const float* __restrict__ Wt, float* __restrict__ hh, float* __restrict__ gsh,
    const float* __restrict__ b2s,
    int r4, int c4, int au, int ab,
    int xoff, int yoff, int ty, float* cst, float* r1c, size_t g_base)
{
    float G[16];
    if (do_act) {
        #pragma unroll
        for (int q = 0; q < 4; q++) {
            int u = au + 16 * q;
            G[4*q+0] = gsh[(u      ) * GSTR + yoff + ab];
            G[4*q+1] = gsh[(u +  64) * GSTR + yoff + ab];
            G[4*q+2] = gsh[(u + 128) * GSTR + yoff + ab];
            G[4*q+3] = gsh[(u + 192) * GSTR + yoff + ab];
        }
    }
    ull a0=0,a1=0,a2=0,a3=0,a4=0,a5=0,a6=0,a7=0;
    const float4*     wp = (const float4*)Wt + r4;
    const ulonglong2* hp = (const ulonglong2*)hh + ((xoff >> 2) + c4);

    #pragma unroll
    for (int q = 0; q < 4; q++) {
        if (do_mv) {
            #pragma unroll 8
            for (int k = 32 * q; k < 32 * q + 32; k++) {
                float4 w = wp[k * 64];
                ulonglong2 hv = hp[k * 8];
                ull w0 = splat(w.x), w1 = splat(w.y), w2 = splat(w.z), w3 = splat(w.w);
                ffma2(a0, w0, hv.x); ffma2(a1, w0, hv.y);
                ffma2(a2, w1, hv.x); ffma2(a3, w1, hv.y);
                ffma2(a4, w2, hv.x); ffma2(a5, w2, hv.y);
                ffma2(a6, w3, hv.x); ffma2(a7, w3, hv.y);
            }
        }
        if (do_act) {
            int u = au + 16 * q;
            float gi = G[4*q+0] + b2s[u      ];
            float gf = G[4*q+1] + b2s[u +  64];
            float gg = G[4*q+2] + b2s[u + 128];
            float go = G[4*q+3] + b2s[u + 192];
            float cn = fmaf(sig_fast(gf), cst[q], sig_fast(gi) * tanh_fast(gg));
            cst[q] = cn;
            hh[(64 + u) * NB + yoff + ab] = sig_fast(go) * tanh_fast(cn);
            hh[u * NB + yoff + ab] = r1c[q];   // r1(ty+1), feeds matvec at ty+1
            if (ty + 2 < TLEN)
                r1c[q] = g_r1[g_base + (size_t)(ty + 2) * 2048 + u * NB + yoff + ab];
        }
    }
    if (do_mv) {
        float* g0 = gsh + (r4 * 4) * GSTR + xoff + c4 * 4;
        *(ulonglong2*)(g0           ) = make_ulonglong2(a0, a1);
        *(ulonglong2*)(g0 +   GSTR  ) = make_ulonglong2(a2, a3);
        *(ulonglong2*)(g0 + 2*GSTR  ) = make_ulonglong2(a4, a5);
        *(ulonglong2*)(g0 + 3*GSTR  ) = make_ulonglong2(a6, a7);
    }
}

__global__ void __launch_bounds__(NTHR, 1)
lstm_rec_kernel(const float* __restrict__ x,
                const float* __restrict__ Wih1, const float* __restrict__ Whh1,
                const float* __restrict__ bih1, const float* __restrict__ bhh1,
                const float* __restrict__ Wih2, const float* __restrict__ Whh2,
                const float* __restrict__ bih2, const float* __restrict__ bhh2,
                const float* __restrict__ fc1w, const float* __restrict__ fc1b,
                const float* __restrict__ fc2w, const float* __restrict__ fc2b,
                float* __restrict__ out)
{
    extern __shared__ float sm[];
    float* Wt    = sm;               // [128][256]  32768
    float* hh    = Wt + 32768;       // [128][32]    4096
    float* gsh   = hh + 4096;        // [256][36]    9216
    float* win   = gsh + 9216;       // [32][193]    6176
    float* b1s   = win + NB * WSTR;  // 256
    float* wi1s  = b1s + 256;        // 256
    float* b2s   = wi1s + 256;       // 256
    float* wcomb = b2s + 256;        // 65
    float* bcs   = wcomb + 65;       // 1
    float* dsh   = bcs + 1;          // 32

    const int tid = threadIdx.x;
    const int b0  = blockIdx.x * NB;
    const int r4  = tid >> 2, c4 = tid & 3;    // matvec role: rows 4*r4.., batch-quad c4
    const int au  = tid >> 4, ab = tid & 15;   // act role: units au+16q, batch-in-half ab
    const size_t g_base = (size_t)blockIdx.x * TLEN * 2048;

    // ---------------- one-time init ----------------
    for (int i = tid; i < NB * TLEN; i += NTHR) {
        int b = i / TLEN, t = i - b * TLEN;
        win[b * WSTR + t] = x[(size_t)(b0 + b) * SEQ + t];
    }
    if (tid < NB) dsh[tid] = x[(size_t)(b0 + tid) * SEQ + TLEN];
    b1s[tid]  = bih1[tid] + bhh1[tid];
    wi1s[tid] = Wih1[tid];
    b2s[tid]  = bih2[tid] + bhh2[tid];
    if (tid < 65) {
        float s = 0.0f;
        for (int j = 0; j < 64; j++) s = fmaf(fc2w[j], fc1w[j * 65 + tid], s);
        wcomb[tid] = s;
    }
    if (tid == 65) {
        float s = fc2b[0];
        for (int j = 0; j < 64; j++) s = fmaf(fc2w[j], fc1b[j], s);
        *bcs = s;
    }

    float cA[4], cB[4], r1A[4], r1B[4];
    __syncthreads();

    for (int step = 0; step < NSTEPS; step++) {
        // ---- stage W1 transposed (thread-per-row: conflict-free STS) ----
        {
            const float4* src = (const float4*)(Whh1 + tid * 64);
            #pragma unroll
            for (int q = 0; q < 16; q++) {
                float4 v = src[q];
                Wt[(4*q    ) * 256 + tid] = v.x;
                Wt[(4*q + 1) * 256 + tid] = v.y;
                Wt[(4*q + 2) * 256 + tid] = v.z;
                Wt[(4*q + 3) * 256 + tid] = v.w;
            }
        }
        for (int i = tid; i < 64 * NB; i += NTHR) hh[i] = 0.0f;
        #pragma unroll
        for (int q = 0; q < 4; q++) { cA[q] = 0.0f; cB[q] = 0.0f; }
        __syncthreads();

        // ============ layer 1 (pipelined halves) ============
        phaseL1(true, false, Wt, hh, gsh, win, b1s, wi1s, r4, c4, au, ab,
                0, 0, 0, step, cA, g_base);                       // matvec_A(0)
        __syncthreads();
        for (int t = 0; t < TLEN; t++) {
            phaseL1(true, true, Wt, hh, gsh, win, b1s, wi1s, r4, c4, au, ab,
                    16, 0, t, step, cA, g_base);                  // matvec_B(t) | act_A(t)
            __syncthreads();
            phaseL1(t + 1 < TLEN, true, Wt, hh, gsh, win, b1s, wi1s, r4, c4, au, ab,
                    0, 16, t, step, cB, g_base);                  // matvec_A(t+1) | act_B(t)
            __syncthreads();
        }

        // ---- transition: h2_0 = h1_T, r1(0) into rows 0..63, stage W2 ----
        #pragma unroll
        for (int q = 0; q < 4; q++) {
            int u = au + 16 * q;
            float hA = hh[u * NB + ab];
            float hB = hh[u * NB + 16 + ab];
            hh[(64 + u) * NB + ab]      = hA;
            hh[(64 + u) * NB + 16 + ab] = hB;
            hh[u * NB + ab]      = g_r1[g_base + u * NB + ab];
            hh[u * NB + 16 + ab] = g_r1[g_base + u * NB + 16 + ab];
            r1A[q] = g_r1[g_base + 2048 + u * NB + ab];
            r1B[q] = g_r1[g_base + 2048 + u * NB + 16 + ab];
        }
        {
            const float4* s1 = (const float4*)(Wih2 + tid * 64);
            const float4* s2 = (const float4*)(Whh2 + tid * 64);
            #pragma unroll
            for (int q = 0; q < 16; q++) {
                float4 v = s1[q];
                Wt[(4*q    ) * 256 + tid] = v.x;
                Wt[(4*q + 1) * 256 + tid] = v.y;
                Wt[(4*q + 2) * 256 + tid] = v.z;
                Wt[(4*q + 3) * 256 + tid] = v.w;
                float4 w = s2[q];
                Wt[(64 + 4*q    ) * 256 + tid] = w.x;
                Wt[(64 + 4*q + 1) * 256 + tid] = w.y;
                Wt[(64 + 4*q + 2) * 256 + tid] = w.z;
                Wt[(64 + 4*q + 3) * 256 + tid] = w.w;
            }
        }
        __syncthreads();

        // ============ layer 2 (pipelined halves) ============
        phaseL2(true, false, Wt, hh, gsh, b2s, r4, c4, au, ab,
                0, 0, 0, cA, r1A, g_base);                        // matvec_A(0)
        __syncthreads();
        for (int t = 0; t < TLEN; t++) {
            phaseL2(true, true, Wt, hh, gsh, b2s, r4, c4, au, ab,
                    16, 0, t, cA, r1A, g_base);                   // matvec_B(t) | act_A(t)
            __syncthreads();
            phaseL2(t + 1 < TLEN, true, Wt, hh, gsh, b2s, r4, c4, au, ab,
                    0, 16, t, cB, r1B, g_base);                   // matvec_A(t+1) | act_B(t)
            __syncthreads();
        }

        // ============ FC (collapsed) + window append ============
        if (tid < NB) {
            float s = *bcs + wcomb[64] * dsh[tid];
            #pragma unroll
            for (int u = 0; u < 64; u++)
                s = fmaf(wcomb[u], fmaxf(hh[(64 + u) * NB + tid], 0.0f), s);
            out[(size_t)(b0 + tid) * NSTEPS + step] = s;
            win[tid * WSTR + TLEN + step] = s;
        }
        __syncthreads();
    }
}

extern "C" void kernel_launch(void* const* d_in, const int* in_sizes, int n_in,
                              void* d_out, int out_size) {
    (void)in_sizes; (void)n_in; (void)out_size;
    const float* x    = (const float*)d_in[0];
    const float* Wih1 = (const float*)d_in[1];
    const float* Whh1 = (const float*)d_in[2];
    const float* bih1 = (const float*)d_in[3];
    const float* bhh1 = (const float*)d_in[4];
    const float* Wih2 = (const float*)d_in[5];
    const float* Whh2 = (const float*)d_in[6];
    const float* bih2 = (const float*)d_in[7];
    const float* bhh2 = (const float*)d_in[8];
    const float* fc1w = (const float*)d_in[9];
    const float* fc1b = (const float*)d_in[10];
    const float* fc2w = (const float*)d_in[11];
    const float* fc2b = (const float*)d_in[12];
    float* out = (float*)d_out;

    size_t smem = (size_t)(32768 + 4096 + 9216 + NB * WSTR + 256 * 3 + 65 + 1 + NB) * sizeof(float);
    cudaFuncSetAttribute(lstm_rec_kernel, cudaFuncAttributeMaxDynamicSharedMemorySize, (int)smem);
    lstm_rec_kernel<<<GRID, NTHR, smem>>>(x, Wih1, Whh1, bih1, bhh1,
                                          Wih2, Whh2, bih2, bhh2,
                                          fc1w, fc1b, fc2w, fc2b, out);
}

// round 4
// speedup vs baseline: 1.1744x; 1.1744x over previous
#include <cuda_runtime.h>

typedef unsigned long long ull;

#define NTHR   256
#define TLEN   168
#define SEQ    169
#define NB     32
#define GRID   128
#define NSTEPS 24
#define WSTR   193
#define GSTR   36
#define GOFF(r) ((r) * GSTR + ((r) >> 3) * 4)   // 4-float skew per 8-row block

// relu(h1) staging: [GRID][TLEN][64][NB]
__device__ float g_r1[(size_t)GRID * TLEN * 64 * NB];

static __device__ __forceinline__ void ffma2(ull& d, ull a, ull b) {
    asm("fma.rn.f32x2 %0, %1, %2, %0;" : "+l"(d) : "l"(a), "l"(b));
}
static __device__ __forceinline__ ull fadd2(ull a, ull b) {
    ull r; asm("add.rn.f32x2 %0, %1, %2;" : "=l"(r) : "l"(a), "l"(b)); return r;
}
static __device__ __forceinline__ ull splat(float w) {
    ull r; asm("mov.b64 %0, {%1, %1};" : "=l"(r) : "f"(w)); return r;
}
static __device__ __forceinline__ float rcp_fast(float x) {
    float r; asm("rcp.approx.f32 %0, %1;" : "=f"(r) : "f"(x)); return r;
}
static __device__ __forceinline__ float sig_fast(float x) { return rcp_fast(1.0f + __expf(-x)); }
static __device__ __forceinline__ float tanh_fast(float x) { return fmaf(2.0f, sig_fast(2.0f * x), -1.0f); }

// g[256 x 32] = Wt[K x 256]^T-view * hh[K x 32]
// thread: rows rg*8..+7, batches bg*8..+7, k-half ks. Cross-ks reduce via shfl_xor(16).
template<int K2>
static __device__ __forceinline__ void matvec8x8(const float* __restrict__ Wt,
                                                 const float* __restrict__ hh,
                                                 float* __restrict__ gsh,
                                                 int rg, int bg, int ks)
{
    ull acc[8][4];
    #pragma unroll
    for (int r = 0; r < 8; r++) {
        #pragma unroll
        for (int c = 0; c < 4; c++) acc[r][c] = 0ull;
    }
    const float4*     wp = (const float4*)Wt + rg * 2 + ks * (K2 * 64);
    const ulonglong2* hp = (const ulonglong2*)hh + bg * 2 + ks * (K2 * 8);

    #pragma unroll 4
    for (int k = 0; k < K2; k++) {
        float4     wA = wp[k * 64];
        float4     wB = wp[k * 64 + 1];
        ulonglong2 hA = hp[k * 8];
        ulonglong2 hB = hp[k * 8 + 1];
        ull s0 = splat(wA.x), s1 = splat(wA.y), s2 = splat(wA.z), s3 = splat(wA.w);
        ull s4 = splat(wB.x), s5 = splat(wB.y), s6 = splat(wB.z), s7 = splat(wB.w);
        ffma2(acc[0][0], s0, hA.x); ffma2(acc[0][1], s0, hA.y); ffma2(acc[0][2], s0, hB.x); ffma2(acc[0][3], s0, hB.y);
        ffma2(acc[1][0], s1, hA.x); ffma2(acc[1][1], s1, hA.y); ffma2(acc[1][2], s1, hB.x); ffma2(acc[1][3], s1, hB.y);
        ffma2(acc[2][0], s2, hA.x); ffma2(acc[2][1], s2, hA.y); ffma2(acc[2][2], s2, hB.x); ffma2(acc[2][3], s2, hB.y);
        ffma2(acc[3][0], s3, hA.x); ffma2(acc[3][1], s3, hA.y); ffma2(acc[3][2], s3, hB.x); ffma2(acc[3][3], s3, hB.y);
        ffma2(acc[4][0], s4, hA.x); ffma2(acc[4][1], s4, hA.y); ffma2(acc[4][2], s4, hB.x); ffma2(acc[4][3], s4, hB.y);
        ffma2(acc[5][0], s5, hA.x); ffma2(acc[5][1], s5, hA.y); ffma2(acc[5][2], s5, hB.x); ffma2(acc[5][3], s5, hB.y);
        ffma2(acc[6][0], s6, hA.x); ffma2(acc[6][1], s6, hA.y); ffma2(acc[6][2], s6, hB.x); ffma2(acc[6][3], s6, hB.y);
        ffma2(acc[7][0], s7, hA.x); ffma2(acc[7][1], s7, hA.y); ffma2(acc[7][2], s7, hB.x); ffma2(acc[7][3], s7, hB.y);
    }
    // reduce across the two k-halves (lane partner = lane ^ 16)
    #pragma unroll
    for (int r = 0; r < 8; r++) {
        #pragma unroll
        for (int c = 0; c < 4; c++)
            acc[r][c] = fadd2(acc[r][c], __shfl_xor_sync(0xffffffffu, acc[r][c], 16));
    }
    // each lane stores 4 of the 8 rows (ks picks which half)
    #pragma unroll
    for (int i = 0; i < 4; i++) {
        ull v0 = ks ? acc[4 + i][0] : acc[i][0];
        ull v1 = ks ? acc[4 + i][1] : acc[i][1];
        ull v2 = ks ? acc[4 + i][2] : acc[i][2];
        ull v3 = ks ? acc[4 + i][3] : acc[i][3];
        int row = rg * 8 + ks * 4 + i;
        float* g0 = gsh + GOFF(row) + bg * 8;
        *(ulonglong2*)(g0)     = make_ulonglong2(v0, v1);
        *(ulonglong2*)(g0 + 4) = make_ulonglong2(v2, v3);
    }
}

__global__ void __launch_bounds__(NTHR, 1)
lstm_rec_kernel(const float* __restrict__ x,
                const float* __restrict__ Wih1, const float* __restrict__ Whh1,
                const float* __restrict__ bih1, const float* __restrict__ bhh1,
                const float* __restrict__ Wih2, const float* __restrict__ Whh2,
                const float* __restrict__ bih2, const float* __restrict__ bhh2,
                const float* __restrict__ fc1w, const float* __restrict__ fc1b,
                const float* __restrict__ fc2w, const float* __restrict__ fc2b,
                float* __restrict__ out)
{
    extern __shared__ float sm[];
    float* Wt    = sm;                // [128][256]      32768
    float* hh    = Wt + 32768;        // [128][32]        4096
    float* gsh   = hh + 4096;         // 256*36 + 32*4 =  9344
    float* win   = gsh + 9344;        // [32][193]        6176
    float* b1s   = win + NB * WSTR;   // 256
    float* wi1s  = b1s + 256;         // 256
    float* b2s   = wi1s + 256;        // 256
    float* wcomb = b2s + 256;         // 65
    float* bcs   = wcomb + 65;        // 1
    float* dsh   = bcs + 1;           // 32

    const int tid = threadIdx.x;
    const int b0  = blockIdx.x * NB;
    const int bg  = tid & 3;
    const int ks  = (tid >> 4) & 1;
    const int rg  = ((tid >> 5) << 2) | ((tid >> 2) & 3);
    const int ab  = tid & 31, au0 = tid >> 5;   // act role: batch ab, units au0+8q
    const size_t g_base = (size_t)blockIdx.x * TLEN * 2048;

    // ---------------- one-time init ----------------
    for (int i = tid; i < NB * TLEN; i += NTHR) {
        int b = i / TLEN, t = i - b * TLEN;
        win[b * WSTR + t] = x[(size_t)(b0 + b) * SEQ + t];
    }
    if (tid < NB) dsh[tid] = x[(size_t)(b0 + tid) * SEQ + TLEN];
    b1s[tid]  = bih1[tid] + bhh1[tid];
    wi1s[tid] = Wih1[tid];
    b2s[tid]  = bih2[tid] + bhh2[tid];
    if (tid < 65) {
        float s = 0.0f;
        for (int j = 0; j < 64; j++) s = fmaf(fc2w[j], fc1w[j * 65 + tid], s);
        wcomb[tid] = s;
    }
    if (tid == 65) {
        float s = fc2b[0];
        for (int j = 0; j < 64; j++) s = fmaf(fc2w[j], fc1b[j], s);
        *bcs = s;
    }

    float cst[8], r1n[8];
    __syncthreads();

    for (int step = 0; step < NSTEPS; step++) {
        // ---- stage W1 transposed (conflict-free), zero h1, zero c ----
        {
            const float4* src = (const float4*)(Whh1 + tid * 64);
            #pragma unroll
            for (int q = 0; q < 16; q++) {
                float4 v = src[q];
                Wt[(4*q    ) * 256 + tid] = v.x;
                Wt[(4*q + 1) * 256 + tid] = v.y;
                Wt[(4*q + 2) * 256 + tid] = v.z;
                Wt[(4*q + 3) * 256 + tid] = v.w;
            }
        }
        for (int i = tid; i < 64 * NB; i += NTHR) hh[i] = 0.0f;
        #pragma unroll
        for (int q = 0; q < 8; q++) cst[q] = 0.0f;
        __syncthreads();

        // ============ layer 1 recurrence ============
        for (int t = 0; t < TLEN; t++) {
            matvec8x8<32>(Wt, hh, gsh, rg, bg, ks);
            __syncthreads();
            float xt = win[ab * WSTR + step + t];
            size_t gb = g_base + (size_t)t * 2048;
            #pragma unroll
            for (int q = 0; q < 8; q++) {
                int u = au0 + (q << 3);
                float gi = gsh[GOFF(u      ) + ab] + fmaf(xt, wi1s[u      ], b1s[u      ]);
                float gf = gsh[GOFF(u +  64) + ab] + fmaf(xt, wi1s[u +  64], b1s[u +  64]);
                float gg = gsh[GOFF(u + 128) + ab] + fmaf(xt, wi1s[u + 128], b1s[u + 128]);
                float go = gsh[GOFF(u + 192) + ab] + fmaf(xt, wi1s[u + 192], b1s[u + 192]);
                float cn = fmaf(sig_fast(gf), cst[q], sig_fast(gi) * tanh_fast(gg));
                cst[q] = cn;
                float h = sig_fast(go) * tanh_fast(cn);
                hh[u * NB + ab] = h;
                g_r1[gb + u * NB + ab] = fmaxf(h, 0.0f);
            }
            __syncthreads();
        }

        // ---- transition: h2_0 = h1_T, rows 0..63 <- r1(0); stage W2 ----
        float h1T[8];
        #pragma unroll
        for (int q = 0; q < 8; q++) {
            int u = au0 + (q << 3);
            h1T[q] = hh[u * NB + ab];
            r1n[q] = g_r1[g_base + u * NB + ab];
        }
        {
            const float4* s1 = (const float4*)(Wih2 + tid * 64);
            const float4* s2 = (const float4*)(Whh2 + tid * 64);
            #pragma unroll
            for (int q = 0; q < 16; q++) {
                float4 v = s1[q];
                Wt[(4*q    ) * 256 + tid] = v.x;
                Wt[(4*q + 1) * 256 + tid] = v.y;
                Wt[(4*q + 2) * 256 + tid] = v.z;
                Wt[(4*q + 3) * 256 + tid] = v.w;
                float4 w = s2[q];
                Wt[(64 + 4*q    ) * 256 + tid] = w.x;
                Wt[(64 + 4*q + 1) * 256 + tid] = w.y;
                Wt[(64 + 4*q + 2) * 256 + tid] = w.z;
                Wt[(64 + 4*q + 3) * 256 + tid] = w.w;
            }
        }
        #pragma unroll
        for (int q = 0; q < 8; q++) {
            int u = au0 + (q << 3);
            hh[(64 + u) * NB + ab] = h1T[q];
            hh[u * NB + ab]        = r1n[q];
        }
        __syncthreads();

        // ============ layer 2 recurrence ============
        for (int t = 0; t < TLEN; t++) {
            if (t + 1 < TLEN) {   // prefetch r1(t+1) under the matvec
                size_t gb = g_base + (size_t)(t + 1) * 2048;
                #pragma unroll
                for (int q = 0; q < 8; q++) {
                    int u = au0 + (q << 3);
                    r1n[q] = g_r1[gb + u * NB + ab];
                }
            }
            matvec8x8<64>(Wt, hh, gsh, rg, bg, ks);
            __syncthreads();
            #pragma unroll
            for (int q = 0; q < 8; q++) {
                int u = au0 + (q << 3);
                float gi = gsh[GOFF(u      ) + ab] + b2s[u      ];
                float gf = gsh[GOFF(u +  64) + ab] + b2s[u +  64];
                float gg = gsh[GOFF(u + 128) + ab] + b2s[u + 128];
                float go = gsh[GOFF(u + 192) + ab] + b2s[u + 192];
                float cn = fmaf(sig_fast(gf), cst[q], sig_fast(gi) * tanh_fast(gg));
                cst[q] = cn;
                hh[(64 + u) * NB + ab] = sig_fast(go) * tanh_fast(cn);
                if (t + 1 < TLEN) hh[u * NB + ab] = r1n[q];
            }
            __syncthreads();
        }

        // ============ FC (collapsed) + window append ============
        if (tid < NB) {
            float s = *bcs + wcomb[64] * dsh[tid];
            #pragma unroll
            for (int u = 0; u < 64; u++)
                s = fmaf(wcomb[u], fmaxf(hh[(64 + u) * NB + tid], 0.0f), s);
            out[(size_t)(b0 + tid) * NSTEPS + step] = s;
            win[tid * WSTR + TLEN + step] = s;
        }
        __syncthreads();
    }
}

extern "C" void kernel_launch(void* const* d_in, const int* in_sizes, int n_in,
                              void* d_out, int out_size) {
    (void)in_sizes; (void)n_in; (void)out_size;
    const float* x    = (const float*)d_in[0];
    const float* Wih1 = (const float*)d_in[1];
    const float* Whh1 = (const float*)d_in[2];
    const float* bih1 = (const float*)d_in[3];
    const float* bhh1 = (const float*)d_in[4];
    const float* Wih2 = (const float*)d_in[5];
    const float* Whh2 = (const float*)d_in[6];
    const float* bih2 = (const float*)d_in[7];
    const float* bhh2 = (const float*)d_in[8];
    const float* fc1w = (const float*)d_in[9];
    const float* fc1b = (const float*)d_in[10];
    const float* fc2w = (const float*)d_in[11];
    const float* fc2b = (const float*)d_in[12];
    float* out = (float*)d_out;

    size_t smem = (size_t)(32768 + 4096 + 9344 + NB * WSTR + 256 * 3 + 65 + 1 + NB) * sizeof(float);
    cudaFuncSetAttribute(lstm_rec_kernel, cudaFuncAttributeMaxDynamicSharedMemorySize, (int)smem);
    lstm_rec_kernel<<<GRID, NTHR, smem>>>(x, Wih1, Whh1, bih1, bhh1,
                                          Wih2, Whh2, bih2, bhh2,
                                          fc1w, fc1b, fc2w, fc2b, out);
}

// round 5
// speedup vs baseline: 1.2078x; 1.0284x over previous
#include <cuda_runtime.h>

typedef unsigned long long ull;

#define NTHR   256
#define TLEN   168
#define SEQ    169
#define NB     32
#define NBG    16      // batches per group
#define GRID   128
#define NSTEPS 24
#define WSTR   193

// relu(h1) staging: [GRID][TLEN][64][NB]
__device__ float g_r1[(size_t)GRID * TLEN * 64 * NB];

static __device__ __forceinline__ void ffma2(ull& d, ull a, ull b) {
    asm("fma.rn.f32x2 %0, %1, %2, %0;" : "+l"(d) : "l"(a), "l"(b));
}
static __device__ __forceinline__ ull fadd2(ull a, ull b) {
    ull r; asm("add.rn.f32x2 %0, %1, %2;" : "=l"(r) : "l"(a), "l"(b)); return r;
}
static __device__ __forceinline__ float rcp_fast(float x) {
    float r; asm("rcp.approx.f32 %0, %1;" : "=f"(r) : "f"(x)); return r;
}
static __device__ __forceinline__ float sig_fast(float x) { return rcp_fast(1.0f + __expf(-x)); }
static __device__ __forceinline__ float tanh_fast(float x) { return fmaf(2.0f, sig_fast(2.0f * x), -1.0f); }

#define GBAR(id) asm volatile("bar.sync %0, %1;" :: "r"(id), "r"(128) : "memory")

// Group matvec: g[256 x 16] = Wt[K x 256]^T-view * hhg[K x 16]
// thread: rows rg*8..+7, batch-octet bg (8 f32), k-half ks; reduce via shfl_xor(16).
// gsh layout: row pitch 16 f32, quad-swizzled: addr = row*16 + 4*((colq)^( (row>>3)&3 )) + col&3
template<int K2>
static __device__ __forceinline__ void matvecG(const float* __restrict__ Wt,
                                               const float* __restrict__ hhg,
                                               float* __restrict__ gshg,
                                               int rg, int bg, int ks)
{
    ull acc[8][4];
    #pragma unroll
    for (int r = 0; r < 8; r++) {
        #pragma unroll
        for (int c = 0; c < 4; c++) acc[r][c] = 0ull;
    }
    const float4*     wp = (const float4*)Wt + rg * 2 + ks * (K2 * 64);
    const ulonglong2* hp = (const ulonglong2*)hhg + bg * 2 + ks * (K2 * 4);

    #pragma unroll 4
    for (int k = 0; k < K2; k++) {
        float4     wA = wp[k * 64];
        float4     wB = wp[k * 64 + 1];
        ulonglong2 hA = hp[k * 4];
        ulonglong2 hB = hp[k * 4 + 1];
        ull s0, s1, s2, s3, s4, s5, s6, s7;
        asm("mov.b64 %0, {%1, %1};" : "=l"(s0) : "f"(wA.x));
        asm("mov.b64 %0, {%1, %1};" : "=l"(s1) : "f"(wA.y));
        asm("mov.b64 %0, {%1, %1};" : "=l"(s2) : "f"(wA.z));
        asm("mov.b64 %0, {%1, %1};" : "=l"(s3) : "f"(wA.w));
        asm("mov.b64 %0, {%1, %1};" : "=l"(s4) : "f"(wB.x));
        asm("mov.b64 %0, {%1, %1};" : "=l"(s5) : "f"(wB.y));
        asm("mov.b64 %0, {%1, %1};" : "=l"(s6) : "f"(wB.z));
        asm("mov.b64 %0, {%1, %1};" : "=l"(s7) : "f"(wB.w));
        ffma2(acc[0][0], s0, hA.x); ffma2(acc[0][1], s0, hA.y); ffma2(acc[0][2], s0, hB.x); ffma2(acc[0][3], s0, hB.y);
        ffma2(acc[1][0], s1, hA.x); ffma2(acc[1][1], s1, hA.y); ffma2(acc[1][2], s1, hB.x); ffma2(acc[1][3], s1, hB.y);
        ffma2(acc[2][0], s2, hA.x); ffma2(acc[2][1], s2, hA.y); ffma2(acc[2][2], s2, hB.x); ffma2(acc[2][3], s2, hB.y);
        ffma2(acc[3][0], s3, hA.x); ffma2(acc[3][1], s3, hA.y); ffma2(acc[3][2], s3, hB.x); ffma2(acc[3][3], s3, hB.y);
        ffma2(acc[4][0], s4, hA.x); ffma2(acc[4][1], s4, hA.y); ffma2(acc[4][2], s4, hB.x); ffma2(acc[4][3], s4, hB.y);
        ffma2(acc[5][0], s5, hA.x); ffma2(acc[5][1], s5, hA.y); ffma2(acc[5][2], s5, hB.x); ffma2(acc[5][3], s5, hB.y);
        ffma2(acc[6][0], s6, hA.x); ffma2(acc[6][1], s6, hA.y); ffma2(acc[6][2], s6, hB.x); ffma2(acc[6][3], s6, hB.y);
        ffma2(acc[7][0], s7, hA.x); ffma2(acc[7][1], s7, hA.y); ffma2(acc[7][2], s7, hB.x); ffma2(acc[7][3], s7, hB.y);
    }
    // reduce across k-halves (partner lane = lane ^ 16)
    #pragma unroll
    for (int r = 0; r < 8; r++) {
        #pragma unroll
        for (int c = 0; c < 4; c++)
            acc[r][c] = fadd2(acc[r][c], __shfl_xor_sync(0xffffffffu, acc[r][c], 16));
    }
    // lane stores 4 of its 8 rows (ks selects half), quad-swizzled
    int sw = rg & 3;
    int q0 = ((bg * 2)     ^ sw) * 4;
    int q1 = ((bg * 2 + 1) ^ sw) * 4;
    #pragma unroll
    for (int i = 0; i < 4; i++) {
        ull v0 = ks ? acc[4 + i][0] : acc[i][0];
        ull v1 = ks ? acc[4 + i][1] : acc[i][1];
        ull v2 = ks ? acc[4 + i][2] : acc[i][2];
        ull v3 = ks ? acc[4 + i][3] : acc[i][3];
        float* base = gshg + (rg * 8 + ks * 4 + i) * 16;
        *(ulonglong2*)(base + q0) = make_ulonglong2(v0, v1);
        *(ulonglong2*)(base + q1) = make_ulonglong2(v2, v3);
    }
}

__global__ void __launch_bounds__(NTHR, 1)
lstm_rec_kernel(const float* __restrict__ x,
                const float* __restrict__ Wih1, const float* __restrict__ Whh1,
                const float* __restrict__ bih1, const float* __restrict__ bhh1,
                const float* __restrict__ Wih2, const float* __restrict__ Whh2,
                const float* __restrict__ bih2, const float* __restrict__ bhh2,
                const float* __restrict__ fc1w, const float* __restrict__ fc1b,
                const float* __restrict__ fc2w, const float* __restrict__ fc2b,
                float* __restrict__ out)
{
    extern __shared__ float sm[];
    float* Wt    = sm;                // [128][256]      32768
    float* hh    = Wt + 32768;        // 2 x [128][16]    4096
    float* gsh   = hh + 4096;         // 2 x [256][16]    8192
    float* win   = gsh + 8192;        // [32][193]        6176
    float* b1s   = win + NB * WSTR;   // 256
    float* wi1s  = b1s + 256;         // 256
    float* b2s   = wi1s + 256;        // 256
    float* wcomb = b2s + 256;         // 65
    float* bcs   = wcomb + 65;        // 1
    float* dsh   = bcs + 1;           // 32

    const int tid   = threadIdx.x;
    const int b0    = blockIdx.x * NB;
    const int group = tid >> 7;
    const int gtid  = tid & 127;
    const int warp  = gtid >> 5;
    const int lane  = gtid & 31;
    const int ks    = (lane >> 4) & 1;
    const int bg    = lane & 1;
    const int rg    = (warp << 3) | ((lane >> 1) & 7);
    const int au0   = gtid >> 4;            // act: unit base (0..7)
    const int ab    = gtid & 15;            // act: batch within group
    const int ab32  = group * NBG + ab;     // CTA-batch index
    const int barid = 1 + group;

    float* hhg  = hh  + group * 2048;       // [128][16]
    float* gshg = gsh + group * 4096;       // [256][16] swizzled
    const size_t g_base = (size_t)blockIdx.x * TLEN * 2048;

    // act-phase swizzled column per (q&3)
    int csw[4];
    #pragma unroll
    for (int s = 0; s < 4; s++) csw[s] = (((ab >> 2) ^ s) << 2) | (ab & 3);

    // ---------------- one-time init (full CTA) ----------------
    for (int i = tid; i < NB * TLEN; i += NTHR) {
        int b = i / TLEN, t = i - b * TLEN;
        win[b * WSTR + t] = x[(size_t)(b0 + b) * SEQ + t];
    }
    if (tid < NB) dsh[tid] = x[(size_t)(b0 + tid) * SEQ + TLEN];
    b1s[tid]  = bih1[tid] + bhh1[tid];
    wi1s[tid] = Wih1[tid];
    b2s[tid]  = bih2[tid] + bhh2[tid];
    if (tid < 65) {
        float s = 0.0f;
        for (int j = 0; j < 64; j++) s = fmaf(fc2w[j], fc1w[j * 65 + tid], s);
        wcomb[tid] = s;
    }
    if (tid == 65) {
        float s = fc2b[0];
        for (int j = 0; j < 64; j++) s = fmaf(fc2w[j], fc1b[j], s);
        *bcs = s;
    }

    float cst[8], r1n[8], h1T[8];
    __syncthreads();

    for (int step = 0; step < NSTEPS; step++) {
        // ---- stage W1 transposed (full CTA), zero h1 rows, zero c ----
        {
            const float4* src = (const float4*)(Whh1 + tid * 64);
            #pragma unroll
            for (int q = 0; q < 16; q++) {
                float4 v = src[q];
                Wt[(4*q    ) * 256 + tid] = v.x;
                Wt[(4*q + 1) * 256 + tid] = v.y;
                Wt[(4*q + 2) * 256 + tid] = v.z;
                Wt[(4*q + 3) * 256 + tid] = v.w;
            }
        }
        for (int i = tid; i < 2048; i += NTHR)
            hh[(i >> 10) * 2048 + (i & 1023)] = 0.0f;   // rows 0..63 of both groups
        #pragma unroll
        for (int q = 0; q < 8; q++) cst[q] = 0.0f;
        __syncthreads();

        // ============ layer 1 recurrence (group-local sync) ============
        for (int t = 0; t < TLEN; t++) {
            matvecG<32>(Wt, hhg, gshg, rg, bg, ks);
            GBAR(barid);
            float xt = win[ab32 * WSTR + step + t];
            size_t gb = g_base + (size_t)t * 2048;
            #pragma unroll
            for (int q = 0; q < 8; q++) {
                int u = au0 + (q << 3);
                const float* gp = gshg + u * 16 + csw[q & 3];
                float gi = gp[0]    + fmaf(xt, wi1s[u      ], b1s[u      ]);
                float gf = gp[1024] + fmaf(xt, wi1s[u +  64], b1s[u +  64]);
                float gg = gp[2048] + fmaf(xt, wi1s[u + 128], b1s[u + 128]);
                float go = gp[3072] + fmaf(xt, wi1s[u + 192], b1s[u + 192]);
                float cn = fmaf(sig_fast(gf), cst[q], sig_fast(gi) * tanh_fast(gg));
                cst[q] = cn;
                float h = sig_fast(go) * tanh_fast(cn);
                hhg[u * NBG + ab] = h;
                g_r1[gb + u * NB + ab32] = fmaxf(h, 0.0f);
            }
            GBAR(barid);
        }

        // ---- transition (own-thread cells) + stage W2 ----
        #pragma unroll
        for (int q = 0; q < 8; q++) {
            int u = au0 + (q << 3);
            h1T[q] = hhg[u * NBG + ab];
            r1n[q] = g_r1[g_base + 2048 + u * NB + ab32];   // r1(t=1)
        }
        float r1z[8];
        #pragma unroll
        for (int q = 0; q < 8; q++) {
            int u = au0 + (q << 3);
            r1z[q] = g_r1[g_base + u * NB + ab32];          // r1(t=0)
        }
        __syncthreads();   // both groups done reading W1
        {
            const float4* s1 = (const float4*)(Wih2 + tid * 64);
            const float4* s2 = (const float4*)(Whh2 + tid * 64);
            #pragma unroll
            for (int q = 0; q < 16; q++) {
                float4 v = s1[q];
                Wt[(4*q    ) * 256 + tid] = v.x;
                Wt[(4*q + 1) * 256 + tid] = v.y;
                Wt[(4*q + 2) * 256 + tid] = v.z;
                Wt[(4*q + 3) * 256 + tid] = v.w;
                float4 w = s2[q];
                Wt[(64 + 4*q    ) * 256 + tid] = w.x;
                Wt[(64 + 4*q + 1) * 256 + tid] = w.y;
                Wt[(64 + 4*q + 2) * 256 + tid] = w.z;
                Wt[(64 + 4*q + 3) * 256 + tid] = w.w;
            }
        }
        #pragma unroll
        for (int q = 0; q < 8; q++) {
            int u = au0 + (q << 3);
            hhg[(64 + u) * NBG + ab] = h1T[q];   // h2_0 = h1_T
            hhg[u * NBG + ab]        = r1z[q];   // r1(0)
        }
        __syncthreads();

        // ============ layer 2 recurrence (group-local sync) ============
        for (int t = 0; t < TLEN; t++) {
            if (t + 1 < TLEN) {   // prefetch r1(t+1) under the matvec
                size_t gb = g_base + (size_t)(t + 1) * 2048;
                #pragma unroll
                for (int q = 0; q < 8; q++) {
                    int u = au0 + (q << 3);
                    r1n[q] = g_r1[gb + u * NB + ab32];
                }
            }
            matvecG<64>(Wt, hhg, gshg, rg, bg, ks);
            GBAR(barid);
            #pragma unroll
            for (int q = 0; q < 8; q++) {
                int u = au0 + (q << 3);
                const float* gp = gshg + u * 16 + csw[q & 3];
                float gi = gp[0]    + b2s[u      ];
                float gf = gp[1024] + b2s[u +  64];
                float gg = gp[2048] + b2s[u + 128];
                float go = gp[3072] + b2s[u + 192];
                float cn = fmaf(sig_fast(gf), cst[q], sig_fast(gi) * tanh_fast(gg));
                cst[q] = cn;
                hhg[(64 + u) * NBG + ab] = sig_fast(go) * tanh_fast(cn);
                if (t + 1 < TLEN) hhg[u * NBG + ab] = r1n[q];
            }
            GBAR(barid);
        }

        // ============ FC (collapsed) + window append (per group) ============
        if (gtid < NBG) {
            int b = group * NBG + gtid;
            float s = *bcs + wcomb[64] * dsh[b];
            #pragma unroll
            for (int u = 0; u < 64; u++)
                s = fmaf(wcomb[u], fmaxf(hhg[(64 + u) * NBG + gtid], 0.0f), s);
            out[(size_t)(b0 + b) * NSTEPS + step] = s;
            win[b * WSTR + TLEN + step] = s;
        }
        __syncthreads();
    }
}

extern "C" void kernel_launch(void* const* d_in, const int* in_sizes, int n_in,
                              void* d_out, int out_size) {
    (void)in_sizes; (void)n_in; (void)out_size;
    const float* x    = (const float*)d_in[0];
    const float* Wih1 = (const float*)d_in[1];
    const float* Whh1 = (const float*)d_in[2];
    const float* bih1 = (const float*)d_in[3];
    const float* bhh1 = (const float*)d_in[4];
    const float* Wih2 = (const float*)d_in[5];
    const float* Whh2 = (const float*)d_in[6];
    const float* bih2 = (const float*)d_in[7];
    const float* bhh2 = (const float*)d_in[8];
    const float* fc1w = (const float*)d_in[9];
    const float* fc1b = (const float*)d_in[10];
    const float* fc2w = (const float*)d_in[11];
    const float* fc2b = (const float*)d_in[12];
    float* out = (float*)d_out;

    size_t smem = (size_t)(32768 + 4096 + 8192 + NB * WSTR + 256 * 3 + 65 + 1 + NB) * sizeof(float);
    cudaFuncSetAttribute(lstm_rec_kernel, cudaFuncAttributeMaxDynamicSharedMemorySize, (int)smem);
    lstm_rec_kernel<<<GRID, NTHR, smem>>>(x, Wih1, Whh1, bih1, bhh1,
                                          Wih2, Whh2, bih2, bhh2,
                                          fc1w, fc1b, fc2w, fc2b, out);
}

// round 6
// speedup vs baseline: 1.2085x; 1.0006x over previous
#include <cuda_runtime.h>

typedef unsigned long long ull;

#define NTHR   256
#define TLEN   168
#define SEQ    169
#define NB     32
#define NBG    16      // batches per group
#define GRID   128
#define NSTEPS 24
#define WSTR   193

// relu(h1) staging: [GRID][TLEN][64][NB]
__device__ float g_r1[(size_t)GRID * TLEN * 64 * NB];

static __device__ __forceinline__ void ffma2(ull& d, ull a, ull b) {
    asm("fma.rn.f32x2 %0, %1, %2, %0;" : "+l"(d) : "l"(a), "l"(b));
}
static __device__ __forceinline__ ull fadd2(ull a, ull b) {
    ull r; asm("add.rn.f32x2 %0, %1, %2;" : "=l"(r) : "l"(a), "l"(b)); return r;
}
static __device__ __forceinline__ float rcp_fast(float x) {
    float r; asm("rcp.approx.f32 %0, %1;" : "=f"(r) : "f"(x)); return r;
}
static __device__ __forceinline__ float sig_fast(float x) { return rcp_fast(1.0f + __expf(-x)); }
static __device__ __forceinline__ float tanh_fast(float x) { return fmaf(2.0f, sig_fast(2.0f * x), -1.0f); }

#define GBAR(id) asm volatile("bar.sync %0, %1;" :: "r"(id), "r"(128) : "memory")

// Group matvec: g[256 x 16] = Wt[K x 256]^T-view * hhg[K x 16]
// thread: rows rg*8..+7, batch-octet bg (8 f32), k-half ks; reduce via shfl_xor(16).
// gsh layout: row pitch 16 f32, quad-swizzled: addr = row*16 + 4*((colq)^( (row>>3)&3 )) + col&3
template<int K2>
static __device__ __forceinline__ void matvecG(const float* __restrict__ Wt,
                                               const float* __restrict__ hhg,
                                               float* __restrict__ gshg,
                                               int rg, int bg, int ks)
{
    ull acc[8][4];
    #pragma unroll
    for (int r = 0; r < 8; r++) {
        #pragma unroll
        for (int c = 0; c < 4; c++) acc[r][c] = 0ull;
    }
    const float4*     wp = (const float4*)Wt + rg * 2 + ks * (K2 * 64);
    const ulonglong2* hp = (const ulonglong2*)hhg + bg * 2 + ks * (K2 * 4);

    #pragma unroll 4
    for (int k = 0; k < K2; k++) {
        float4     wA = wp[k * 64];
        float4     wB = wp[k * 64 + 1];
        ulonglong2 hA = hp[k * 4];
        ulonglong2 hB = hp[k * 4 + 1];
        ull s0, s1, s2, s3, s4, s5, s6, s7;
        asm("mov.b64 %0, {%1, %1};" : "=l"(s0) : "f"(wA.x));
        asm("mov.b64 %0, {%1, %1};" : "=l"(s1) : "f"(wA.y));
        asm("mov.b64 %0, {%1, %1};" : "=l"(s2) : "f"(wA.z));
        asm("mov.b64 %0, {%1, %1};" : "=l"(s3) : "f"(wA.w));
        asm("mov.b64 %0, {%1, %1};" : "=l"(s4) : "f"(wB.x));
        asm("mov.b64 %0, {%1, %1};" : "=l"(s5) : "f"(wB.y));
        asm("mov.b64 %0, {%1, %1};" : "=l"(s6) : "f"(wB.z));
        asm("mov.b64 %0, {%1, %1};" : "=l"(s7) : "f"(wB.w));
        ffma2(acc[0][0], s0, hA.x); ffma2(acc[0][1], s0, hA.y); ffma2(acc[0][2], s0, hB.x); ffma2(acc[0][3], s0, hB.y);
        ffma2(acc[1][0], s1, hA.x); ffma2(acc[1][1], s1, hA.y); ffma2(acc[1][2], s1, hB.x); ffma2(acc[1][3], s1, hB.y);
        ffma2(acc[2][0], s2, hA.x); ffma2(acc[2][1], s2, hA.y); ffma2(acc[2][2], s2, hB.x); ffma2(acc[2][3], s2, hB.y);
        ffma2(acc[3][0], s3, hA.x); ffma2(acc[3][1], s3, hA.y); ffma2(acc[3][2], s3, hB.x); ffma2(acc[3][3], s3, hB.y);
        ffma2(acc[4][0], s4, hA.x); ffma2(acc[4][1], s4, hA.y); ffma2(acc[4][2], s4, hB.x); ffma2(acc[4][3], s4, hB.y);
        ffma2(acc[5][0], s5, hA.x); ffma2(acc[5][1], s5, hA.y); ffma2(acc[5][2], s5, hB.x); ffma2(acc[5][3], s5, hB.y);
        ffma2(acc[6][0], s6, hA.x); ffma2(acc[6][1], s6, hA.y); ffma2(acc[6][2], s6, hB.x); ffma2(acc[6][3], s6, hB.y);
        ffma2(acc[7][0], s7, hA.x); ffma2(acc[7][1], s7, hA.y); ffma2(acc[7][2], s7, hB.x); ffma2(acc[7][3], s7, hB.y);
    }
    // reduce across k-halves (partner lane = lane ^ 16)
    #pragma unroll
    for (int r = 0; r < 8; r++) {
        #pragma unroll
        for (int c = 0; c < 4; c++)
            acc[r][c] = fadd2(acc[r][c], __shfl_xor_sync(0xffffffffu, acc[r][c], 16));
    }
    // lane stores 4 of its 8 rows (ks selects half), quad-swizzled
    int sw = rg & 3;
    int q0 = ((bg * 2)     ^ sw) * 4;
    int q1 = ((bg * 2 + 1) ^ sw) * 4;
    #pragma unroll
    for (int i = 0; i < 4; i++) {
        ull v0 = ks ? acc[4 + i][0] : acc[i][0];
        ull v1 = ks ? acc[4 + i][1] : acc[i][1];
        ull v2 = ks ? acc[4 + i][2] : acc[i][2];
        ull v3 = ks ? acc[4 + i][3] : acc[i][3];
        float* base = gshg + (rg * 8 + ks * 4 + i) * 16;
        *(ulonglong2*)(base + q0) = make_ulonglong2(v0, v1);
        *(ulonglong2*)(base + q1) = make_ulonglong2(v2, v3);
    }
}

__global__ void __launch_bounds__(NTHR, 1)
lstm_rec_kernel(const float* __restrict__ x,
                const float* __restrict__ Wih1, const float* __restrict__ Whh1,
                const float* __restrict__ bih1, const float* __restrict__ bhh1,
                const float* __restrict__ Wih2, const float* __restrict__ Whh2,
                const float* __restrict__ bih2, const float* __restrict__ bhh2,
                const float* __restrict__ fc1w, const float* __restrict__ fc1b,
                const float* __restrict__ fc2w, const float* __restrict__ fc2b,
                float* __restrict__ out)
{
    extern __shared__ float sm[];
    float* Wt    = sm;                // [128][256]      32768
    float* hh    = Wt + 32768;        // 2 x [128][16]    4096
    float* gsh   = hh + 4096;         // 2 x [256][16]    8192
    float* win   = gsh + 8192;        // [32][193]        6176
    float* b1s   = win + NB * WSTR;   // 256
    float* wi1s  = b1s + 256;         // 256
    float* b2s   = wi1s + 256;        // 256
    float* wcomb = b2s + 256;         // 65
    float* bcs   = wcomb + 65;        // 1
    float* dsh   = bcs + 1;           // 32

    const int tid   = threadIdx.x;
    const int b0    = blockIdx.x * NB;
    const int group = tid >> 7;
    const int gtid  = tid & 127;
    const int warp  = gtid >> 5;
    const int lane  = gtid & 31;
    const int ks    = (lane >> 4) & 1;
    const int bg    = lane & 1;
    const int rg    = (warp << 3) | ((lane >> 1) & 7);
    const int au0   = gtid >> 4;            // act: unit base (0..7)
    const int ab    = gtid & 15;            // act: batch within group
    const int ab32  = group * NBG + ab;     // CTA-batch index
    const int barid = 1 + group;

    float* hhg  = hh  + group * 2048;       // [128][16]
    float* gshg = gsh + group * 4096;       // [256][16] swizzled
    const size_t g_base = (size_t)blockIdx.x * TLEN * 2048;

    // act-phase swizzled column per (q&3)
    int csw[4];
    #pragma unroll
    for (int s = 0; s < 4; s++) csw[s] = (((ab >> 2) ^ s) << 2) | (ab & 3);

    // ---------------- one-time init (full CTA) ----------------
    for (int i = tid; i < NB * TLEN; i += NTHR) {
        int b = i / TLEN, t = i - b * TLEN;
        win[b * WSTR + t] = x[(size_t)(b0 + b) * SEQ + t];
    }
    if (tid < NB) dsh[tid] = x[(size_t)(b0 + tid) * SEQ + TLEN];
    b1s[tid]  = bih1[tid] + bhh1[tid];
    wi1s[tid] = Wih1[tid];
    b2s[tid]  = bih2[tid] + bhh2[tid];
    if (tid < 65) {
        float s = 0.0f;
        for (int j = 0; j < 64; j++) s = fmaf(fc2w[j], fc1w[j * 65 + tid], s);
        wcomb[tid] = s;
    }
    if (tid == 65) {
        float s = fc2b[0];
        for (int j = 0; j < 64; j++) s = fmaf(fc2w[j], fc1b[j], s);
        *bcs = s;
    }

    float cst[8], r1n[8], h1T[8];
    __syncthreads();

    for (int step = 0; step < NSTEPS; step++) {
        // ---- stage W1 transposed (full CTA), zero h1 rows, zero c ----
        {
            const float4* src = (const float4*)(Whh1 + tid * 64);
            #pragma unroll
            for (int q = 0; q < 16; q++) {
                float4 v = src[q];
                Wt[(4*q    ) * 256 + tid] = v.x;
                Wt[(4*q + 1) * 256 + tid] = v.y;
                Wt[(4*q + 2) * 256 + tid] = v.z;
                Wt[(4*q + 3) * 256 + tid] = v.w;
            }
        }
        for (int i = tid; i < 2048; i += NTHR)
            hh[(i >> 10) * 2048 + (i & 1023)] = 0.0f;   // rows 0..63 of both groups
        #pragma unroll
        for (int q = 0; q < 8; q++) cst[q] = 0.0f;
        __syncthreads();

        // ============ layer 1 recurrence (group-local sync) ============
        for (int t = 0; t < TLEN; t++) {
            matvecG<32>(Wt, hhg, gshg, rg, bg, ks);
            GBAR(barid);
            float xt = win[ab32 * WSTR + step + t];
            size_t gb = g_base + (size_t)t * 2048;
            #pragma unroll
            for (int q = 0; q < 8; q++) {
                int u = au0 + (q << 3);
                const float* gp = gshg + u * 16 + csw[q & 3];
                float gi = gp[0]    + fmaf(xt, wi1s[u      ], b1s[u      ]);
                float gf = gp[1024] + fmaf(xt, wi1s[u +  64], b1s[u +  64]);
                float gg = gp[2048] + fmaf(xt, wi1s[u + 128], b1s[u + 128]);
                float go = gp[3072] + fmaf(xt, wi1s[u + 192], b1s[u + 192]);
                float cn = fmaf(sig_fast(gf), cst[q], sig_fast(gi) * tanh_fast(gg));
                cst[q] = cn;
                float h = sig_fast(go) * tanh_fast(cn);
                hhg[u * NBG + ab] = h;
                g_r1[gb + u * NB + ab32] = fmaxf(h, 0.0f);
            }
            GBAR(barid);
        }

        // ---- transition (own-thread cells) + stage W2 ----
        #pragma unroll
        for (int q = 0; q < 8; q++) {
            int u = au0 + (q << 3);
            h1T[q] = hhg[u * NBG + ab];
            r1n[q] = g_r1[g_base + 2048 + u * NB + ab32];   // r1(t=1)
        }
        float r1z[8];
        #pragma unroll
        for (int q = 0; q < 8; q++) {
            int u = au0 + (q << 3);
            r1z[q] = g_r1[g_base + u * NB + ab32];          // r1(t=0)
        }
        __syncthreads();   // both groups done reading W1
        {
            const float4* s1 = (const float4*)(Wih2 + tid * 64);
            const float4* s2 = (const float4*)(Whh2 + tid * 64);
            #pragma unroll
            for (int q = 0; q < 16; q++) {
                float4 v = s1[q];
                Wt[(4*q    ) * 256 + tid] = v.x;
                Wt[(4*q + 1) * 256 + tid] = v.y;
                Wt[(4*q + 2) * 256 + tid] = v.z;
                Wt[(4*q + 3) * 256 + tid] = v.w;
                float4 w = s2[q];
                Wt[(64 + 4*q    ) * 256 + tid] = w.x;
                Wt[(64 + 4*q + 1) * 256 + tid] = w.y;
                Wt[(64 + 4*q + 2) * 256 + tid] = w.z;
                Wt[(64 + 4*q + 3) * 256 + tid] = w.w;
            }
        }
        #pragma unroll
        for (int q = 0; q < 8; q++) {
            int u = au0 + (q << 3);
            hhg[(64 + u) * NBG + ab] = h1T[q];   // h2_0 = h1_T
            hhg[u * NBG + ab]        = r1z[q];   // r1(0)
        }
        __syncthreads();

        // ============ layer 2 recurrence (group-local sync) ============
        for (int t = 0; t < TLEN; t++) {
            if (t + 1 < TLEN) {   // prefetch r1(t+1) under the matvec
                size_t gb = g_base + (size_t)(t + 1) * 2048;
                #pragma unroll
                for (int q = 0; q < 8; q++) {
                    int u = au0 + (q << 3);
                    r1n[q] = g_r1[gb + u * NB + ab32];
                }
            }
            matvecG<64>(Wt, hhg, gshg, rg, bg, ks);
            GBAR(barid);
            #pragma unroll
            for (int q = 0; q < 8; q++) {
                int u = au0 + (q << 3);
                const float* gp = gshg + u * 16 + csw[q & 3];
                float gi = gp[0]    + b2s[u      ];
                float gf = gp[1024] + b2s[u +  64];
                float gg = gp[2048] + b2s[u + 128];
                float go = gp[3072] + b2s[u + 192];
                float cn = fmaf(sig_fast(gf), cst[q], sig_fast(gi) * tanh_fast(gg));
                cst[q] = cn;
                hhg[(64 + u) * NBG + ab] = sig_fast(go) * tanh_fast(cn);
                if (t + 1 < TLEN) hhg[u * NBG + ab] = r1n[q];
            }
            GBAR(barid);
        }

        // ============ FC (collapsed) + window append (per group) ============
        if (gtid < NBG) {
            int b = group * NBG + gtid;
            float s = *bcs + wcomb[64] * dsh[b];
            #pragma unroll
            for (int u = 0; u < 64; u++)
                s = fmaf(wcomb[u], fmaxf(hhg[(64 + u) * NBG + gtid], 0.0f), s);
            out[(size_t)(b0 + b) * NSTEPS + step] = s;
            win[b * WSTR + TLEN + step] = s;
        }
        __syncthreads();
    }
}

extern "C" void kernel_launch(void* const* d_in, const int* in_sizes, int n_in,
                              void* d_out, int out_size) {
    (void)in_sizes; (void)n_in; (void)out_size;
    const float* x    = (const float*)d_in[0];
    const float* Wih1 = (const float*)d_in[1];
    const float* Whh1 = (const float*)d_in[2];
    const float* bih1 = (const float*)d_in[3];
    const float* bhh1 = (const float*)d_in[4];
    const float* Wih2 = (const float*)d_in[5];
    const float* Whh2 = (const float*)d_in[6];
    const float* bih2 = (const float*)d_in[7];
    const float* bhh2 = (const float*)d_in[8];
    const float* fc1w = (const float*)d_in[9];
    const float* fc1b = (const float*)d_in[10];
    const float* fc2w = (const float*)d_in[11];
    const float* fc2b = (const float*)d_in[12];
    float* out = (float*)d_out;

    size_t smem = (size_t)(32768 + 4096 + 8192 + NB * WSTR + 256 * 3 + 65 + 1 + NB) * sizeof(float);
    cudaFuncSetAttribute(lstm_rec_kernel, cudaFuncAttributeMaxDynamicSharedMemorySize, (int)smem);
    lstm_rec_kernel<<<GRID, NTHR, smem>>>(x, Wih1, Whh1, bih1, bhh1,
                                          Wih2, Whh2, bih2, bhh2,
                                          fc1w, fc1b, fc2w, fc2b, out);
}